// round 2
// baseline (speedup 1.0000x reference)
#include <cuda_runtime.h>
#include <cstdint>

// Problem constants (fixed by the dataset)
#define T_TOKENS 2048
#define T_HIDDEN 2048
#define T_INTER  768
#define T_NEXP   16
#define T_TOPK   2
#define T_NPAIRS (T_TOKENS * T_TOPK)   // 4096

// Tiling
#define BM 64
#define BN 64
#define BK 16
#define NTHREADS 256

// -------- device-global scratch (no allocations allowed) --------
__device__ int   g_offs[T_NEXP + 1];
__device__ int   g_tok[T_NPAIRS];
__device__ float g_wt[T_NPAIRS];
__device__ float g_h[(size_t)T_NPAIRS * T_INTER];   // 12.58 MB intermediate activations

// ----------------------------------------------------------------
// Routing: bucket (token, k) pairs by expert. Detects whether the
// top_k_index buffer is int32 or int64 at runtime (odd 32-bit words
// of an int64 buffer with values 0..15 are all zero).
// ----------------------------------------------------------------
__global__ void route_kernel(const int* __restrict__ idx32, const float* __restrict__ w) {
    __shared__ int cnt[T_NEXP];
    __shared__ int base[T_NEXP];
    __shared__ int cur[T_NEXP];
    __shared__ int odd_nonzero;
    int tid = threadIdx.x;
    if (tid < T_NEXP) cnt[tid] = 0;
    if (tid == 0) odd_nonzero = 0;
    __syncthreads();

    // int64 detection: scan first T_NPAIRS 32-bit words (always in-bounds)
    for (int j = tid; j < T_NPAIRS; j += NTHREADS) {
        if ((j & 1) && idx32[j] != 0) odd_nonzero = 1;
    }
    __syncthreads();
    bool i64 = (odd_nonzero == 0);

    for (int p = tid; p < T_NPAIRS; p += NTHREADS) {
        int e = i64 ? idx32[2 * p] : idx32[p];
        atomicAdd(&cnt[e], 1);
    }
    __syncthreads();
    if (tid == 0) {
        int s = 0;
        for (int e = 0; e < T_NEXP; e++) {
            base[e] = s; cur[e] = 0; g_offs[e] = s; s += cnt[e];
        }
        g_offs[T_NEXP] = s;
    }
    __syncthreads();
    for (int p = tid; p < T_NPAIRS; p += NTHREADS) {
        int e = i64 ? idx32[2 * p] : idx32[p];
        int slot = base[e] + atomicAdd(&cur[e], 1);
        g_tok[slot] = p >> 1;      // token index (p = t*TOP_K + k)
        g_wt[slot]  = w[p];
    }
}

// ----------------------------------------------------------------
// Zero the output (d_out is poisoned by the harness).
// ----------------------------------------------------------------
__global__ void zero_kernel(float4* __restrict__ out) {
    int i = blockIdx.x * blockDim.x + threadIdx.x;
    out[i] = make_float4(0.f, 0.f, 0.f, 0.f);
}

// ----------------------------------------------------------------
// GEMM1 (fused gate+up+SwiGLU):
//   h[s, n] = silu(x[tok_s] . Wg[e,n,:]) * (x[tok_s] . Wu[e,n,:])
// A gathered from hidden_states; both operands K-contiguous.
// ----------------------------------------------------------------
__global__ __launch_bounds__(NTHREADS)
void gemm1_kernel(const float* __restrict__ x,
                  const float* __restrict__ Wg,
                  const float* __restrict__ Wu) {
    int e   = blockIdx.z;
    int off = g_offs[e];
    int cnt = g_offs[e + 1] - off;
    int m0  = blockIdx.y * BM;
    if (m0 >= cnt) return;                 // empty tile: exit fast
    int n0  = blockIdx.x * BN;

    const float* wg = Wg + (size_t)e * T_INTER * T_HIDDEN;
    const float* wu = Wu + (size_t)e * T_INTER * T_HIDDEN;

    __shared__ float As[BK][BM];
    __shared__ float Gs[BK][BN];
    __shared__ float Us[BK][BN];

    int tid = threadIdx.x;
    int tx = tid & 15, ty = tid >> 4;      // 16x16 thread grid, 4x4 outputs each
    int lr = tid >> 2;                     // load row 0..63
    int lk = (tid & 3) << 2;               // load k-quad 0,4,8,12

    const float* xrow = nullptr;
    int arow = m0 + lr;
    if (arow < cnt) xrow = x + (size_t)g_tok[off + arow] * T_HIDDEN;
    const float* grow = wg + (size_t)(n0 + lr) * T_HIDDEN;
    const float* urow = wu + (size_t)(n0 + lr) * T_HIDDEN;

    float acc_g[4][4] = {};
    float acc_u[4][4] = {};

    for (int k0 = 0; k0 < T_HIDDEN; k0 += BK) {
        float4 av = xrow ? *(const float4*)(xrow + k0 + lk)
                         : make_float4(0.f, 0.f, 0.f, 0.f);
        float4 gv = *(const float4*)(grow + k0 + lk);
        float4 uv = *(const float4*)(urow + k0 + lk);
        As[lk + 0][lr] = av.x; As[lk + 1][lr] = av.y;
        As[lk + 2][lr] = av.z; As[lk + 3][lr] = av.w;
        Gs[lk + 0][lr] = gv.x; Gs[lk + 1][lr] = gv.y;
        Gs[lk + 2][lr] = gv.z; Gs[lk + 3][lr] = gv.w;
        Us[lk + 0][lr] = uv.x; Us[lk + 1][lr] = uv.y;
        Us[lk + 2][lr] = uv.z; Us[lk + 3][lr] = uv.w;
        __syncthreads();

        #pragma unroll
        for (int kk = 0; kk < BK; kk++) {
            float4 a4 = *(const float4*)&As[kk][ty << 2];
            float4 g4 = *(const float4*)&Gs[kk][tx << 2];
            float4 u4 = *(const float4*)&Us[kk][tx << 2];
            float a[4] = {a4.x, a4.y, a4.z, a4.w};
            float g[4] = {g4.x, g4.y, g4.z, g4.w};
            float u[4] = {u4.x, u4.y, u4.z, u4.w};
            #pragma unroll
            for (int i = 0; i < 4; i++)
                #pragma unroll
                for (int j = 0; j < 4; j++) {
                    acc_g[i][j] += a[i] * g[j];
                    acc_u[i][j] += a[i] * u[j];
                }
        }
        __syncthreads();
    }

    #pragma unroll
    for (int i = 0; i < 4; i++) {
        int r = m0 + (ty << 2) + i;
        if (r < cnt) {
            float* hrow = g_h + (size_t)(off + r) * T_INTER + n0 + (tx << 2);
            #pragma unroll
            for (int j = 0; j < 4; j++) {
                float g = acc_g[i][j];
                float s = g / (1.f + __expf(-g));   // silu
                hrow[j] = s * acc_u[i][j];
            }
        }
    }
}

// ----------------------------------------------------------------
// GEMM2 (down proj + weighted scatter-add):
//   out[tok_s, n] += w_s * (h[s,:] . Wd[e,n,:])
// ----------------------------------------------------------------
__global__ __launch_bounds__(NTHREADS)
void gemm2_kernel(const float* __restrict__ Wd, float* __restrict__ out) {
    int e   = blockIdx.z;
    int off = g_offs[e];
    int cnt = g_offs[e + 1] - off;
    int m0  = blockIdx.y * BM;
    if (m0 >= cnt) return;
    int n0  = blockIdx.x * BN;

    const float* wd = Wd + (size_t)e * T_HIDDEN * T_INTER;

    __shared__ float As[BK][BM];
    __shared__ float Bs[BK][BN];

    int tid = threadIdx.x;
    int tx = tid & 15, ty = tid >> 4;
    int lr = tid >> 2;
    int lk = (tid & 3) << 2;

    const float* hrow = nullptr;
    int arow = m0 + lr;
    if (arow < cnt) hrow = g_h + (size_t)(off + arow) * T_INTER;
    const float* brow = wd + (size_t)(n0 + lr) * T_INTER;

    float acc[4][4] = {};

    for (int k0 = 0; k0 < T_INTER; k0 += BK) {
        float4 av = hrow ? *(const float4*)(hrow + k0 + lk)
                         : make_float4(0.f, 0.f, 0.f, 0.f);
        float4 bv = *(const float4*)(brow + k0 + lk);
        As[lk + 0][lr] = av.x; As[lk + 1][lr] = av.y;
        As[lk + 2][lr] = av.z; As[lk + 3][lr] = av.w;
        Bs[lk + 0][lr] = bv.x; Bs[lk + 1][lr] = bv.y;
        Bs[lk + 2][lr] = bv.z; Bs[lk + 3][lr] = bv.w;
        __syncthreads();

        #pragma unroll
        for (int kk = 0; kk < BK; kk++) {
            float4 a4 = *(const float4*)&As[kk][ty << 2];
            float4 b4 = *(const float4*)&Bs[kk][tx << 2];
            float a[4] = {a4.x, a4.y, a4.z, a4.w};
            float b[4] = {b4.x, b4.y, b4.z, b4.w};
            #pragma unroll
            for (int i = 0; i < 4; i++)
                #pragma unroll
                for (int j = 0; j < 4; j++)
                    acc[i][j] += a[i] * b[j];
        }
        __syncthreads();
    }

    #pragma unroll
    for (int i = 0; i < 4; i++) {
        int r = m0 + (ty << 2) + i;
        if (r < cnt) {
            int   tok = g_tok[off + r];
            float wgt = g_wt[off + r];
            float* orow = out + (size_t)tok * T_HIDDEN + n0 + (tx << 2);
            #pragma unroll
            for (int j = 0; j < 4; j++)
                atomicAdd(&orow[j], wgt * acc[i][j]);
        }
    }
}

// ----------------------------------------------------------------
extern "C" void kernel_launch(void* const* d_in, const int* in_sizes, int n_in,
                              void* d_out, int out_size) {
    const float* x   = (const float*)d_in[0];   // [2048, 2048] fp32
    const int*   idx = (const int*)d_in[1];     // [2048, 2] int32 or int64 (runtime-detected)
    const float* w   = (const float*)d_in[2];   // [2048, 2] fp32
    const float* Wg  = (const float*)d_in[3];   // [16, 768, 2048] fp32
    const float* Wu  = (const float*)d_in[4];   // [16, 768, 2048] fp32
    const float* Wd  = (const float*)d_in[5];   // [16, 2048, 768] fp32
    float* out = (float*)d_out;                 // [2048, 2048] fp32

    route_kernel<<<1, NTHREADS>>>(idx, w);
    zero_kernel<<<(T_TOKENS * T_HIDDEN / 4) / NTHREADS, NTHREADS>>>((float4*)out);
    gemm1_kernel<<<dim3(T_INTER / BN, T_NPAIRS / BM, T_NEXP), NTHREADS>>>(x, Wg, Wu);
    gemm2_kernel<<<dim3(T_HIDDEN / BN, T_NPAIRS / BM, T_NEXP), NTHREADS>>>(Wd, out);
}